// round 15
// baseline (speedup 1.0000x reference)
#include <cuda_runtime.h>
#include <cuda_bf16.h>
#include <cstdint>

#define NPTS 4096
#define NROWS_TOT 16384
#define INV_RENORM (1.0f / 1.004096f)
#define NEG_HALF_L2E (-0.72134752f)
#define SQRT_L2E 1.2011224087f

// degree-4 poly of 24000*exp(x) on [0,1], abs err ~1 count
#define PA0 24000.62f
#define PA1 23969.11f
#define PA2 12239.55f
#define PA3 3359.48f
#define PA4 1669.28f

#define ASTR 72
#define BSTR 72
#define NSTR 136

// ---- device-global scratch ----
__device__ __align__(16) unsigned short g_zhi[NROWS_TOT * 64];
__device__ __align__(16) unsigned short g_zlo[NROWS_TOT * 64];
__device__ __align__(16) float          g_sq [NROWS_TOT];      // -log2e/2 * ||z||^2
__device__ __align__(16) unsigned short g_num[(size_t)NROWS_TOT * NPTS];
__device__ __align__(16) float          g_scale[NROWS_TOT];

// ---- PTX helpers ----
__device__ __forceinline__ void ldsm_x4(uint32_t addr, uint32_t* r) {
    asm volatile("ldmatrix.sync.aligned.m8n8.x4.shared.b16 {%0,%1,%2,%3}, [%4];"
                 : "=r"(r[0]), "=r"(r[1]), "=r"(r[2]), "=r"(r[3]) : "r"(addr));
}
__device__ __forceinline__ void mma_bf16(float* d, const uint32_t* a, const uint32_t* b) {
    asm volatile(
        "mma.sync.aligned.m16n8k16.row.col.f32.bf16.bf16.f32 "
        "{%0,%1,%2,%3},{%4,%5,%6,%7},{%8,%9},{%0,%1,%2,%3};"
        : "+f"(d[0]), "+f"(d[1]), "+f"(d[2]), "+f"(d[3])
        : "r"(a[0]), "r"(a[1]), "r"(a[2]), "r"(a[3]), "r"(b[0]), "r"(b[1]));
}
__device__ __forceinline__ void cp16(uint32_t dst, const void* src) {
    asm volatile("cp.async.cg.shared.global [%0], [%1], 16;" :: "r"(dst), "l"(src));
}
__device__ __forceinline__ void cp4(uint32_t dst, const void* src) {
    asm volatile("cp.async.ca.shared.global [%0], [%1], 4;" :: "r"(dst), "l"(src));
}
__device__ __forceinline__ void cp_commit() { asm volatile("cp.async.commit_group;"); }
__device__ __forceinline__ void cp_wait0()  { asm volatile("cp.async.wait_group 0;"); }

__device__ __forceinline__ void bsplit(float v, unsigned short& h, unsigned short& l) {
    __nv_bfloat16 hh = __float2bfloat16(v);
    float hf = __bfloat162float(hh);
    __nv_bfloat16 ll = __float2bfloat16(v - hf);
    h = __bfloat16_as_ushort(hh);
    l = __bfloat16_as_ushort(ll);
}
__device__ __forceinline__ uint32_t smem_u32(const void* p) {
    uint32_t a;
    asm("{ .reg .u64 tt; cvta.to.shared.u64 tt, %1; cvt.u32.u64 %0, tt; }" : "=r"(a) : "l"(p));
    return a;
}

// ===========================================================================
// Kernel 1: MLP 256 -> 128 -> 64 -> 50, f-blocked x2 (R8/R11-proven).
// 32 rows/CTA, 512 threads, grid 512. Layer-1 unroll deepened to 4.
// ===========================================================================
#define MLP_SMEM 64000

__global__ __launch_bounds__(512) void mlp_kernel(
    const float* __restrict__ emb,
    const float* __restrict__ W1, const float* __restrict__ b1,
    const float* __restrict__ W2, const float* __restrict__ b2,
    const float* __restrict__ W3, const float* __restrict__ b3)
{
    extern __shared__ char msm[];
    float (*E_s)[256]  = (float(*)[256])(msm);
    float (*h1_s)[128] = (float(*)[128])(msm + 32768);
    float (*h2_s)[64]  = (float(*)[64]) (msm + 49152);
    float (*z_s)[52]   = (float(*)[52]) (msm + 57344);

    const int t = threadIdx.x;
    const size_t rowbase = (size_t)blockIdx.x * 32;

    {
        const float4* src = (const float4*)(emb + rowbase * 256);
        float4* dst = (float4*)&E_s[0][0];
        #pragma unroll
        for (int i = 0; i < 4; i++) dst[t + i * 512] = src[t + i * 512];
    }
    __syncthreads();

    // layer 1: 256 -> 128, relu.  f-pair = (t&63)*2, rows (t>>6)*4..+3
    {
        const int f0 = (t & 63) * 2, rg = (t >> 6) * 4;
        float acc[4][2];
        #pragma unroll
        for (int r = 0; r < 4; r++) { acc[r][0] = 0.f; acc[r][1] = 0.f; }
        const float* w = W1 + f0;
        #pragma unroll 4
        for (int d = 0; d < 256; d += 4) {
            float2 w0 = *(const float2*)&w[(d + 0) * 128];
            float2 w1 = *(const float2*)&w[(d + 1) * 128];
            float2 w2 = *(const float2*)&w[(d + 2) * 128];
            float2 w3 = *(const float2*)&w[(d + 3) * 128];
            #pragma unroll
            for (int r = 0; r < 4; r++) {
                float4 e = *(const float4*)&E_s[rg + r][d];
                acc[r][0] = fmaf(e.x, w0.x, acc[r][0]); acc[r][1] = fmaf(e.x, w0.y, acc[r][1]);
                acc[r][0] = fmaf(e.y, w1.x, acc[r][0]); acc[r][1] = fmaf(e.y, w1.y, acc[r][1]);
                acc[r][0] = fmaf(e.z, w2.x, acc[r][0]); acc[r][1] = fmaf(e.z, w2.y, acc[r][1]);
                acc[r][0] = fmaf(e.w, w3.x, acc[r][0]); acc[r][1] = fmaf(e.w, w3.y, acc[r][1]);
            }
        }
        const float2 bb = *(const float2*)&b1[f0];
        #pragma unroll
        for (int r = 0; r < 4; r++) {
            float2 hv;
            hv.x = fmaxf(acc[r][0] + bb.x, 0.f);
            hv.y = fmaxf(acc[r][1] + bb.y, 0.f);
            *(float2*)&h1_s[rg + r][f0] = hv;
        }
    }
    __syncthreads();

    // layer 2: 128 -> 64, relu
    {
        const int f0 = (t & 31) * 2, rg = (t >> 5) * 2;
        float acc[2][2];
        acc[0][0] = acc[0][1] = acc[1][0] = acc[1][1] = 0.f;
        const float* w = W2 + f0;
        #pragma unroll 2
        for (int d = 0; d < 128; d += 4) {
            float2 w0 = *(const float2*)&w[(d + 0) * 64];
            float2 w1 = *(const float2*)&w[(d + 1) * 64];
            float2 w2 = *(const float2*)&w[(d + 2) * 64];
            float2 w3 = *(const float2*)&w[(d + 3) * 64];
            #pragma unroll
            for (int r = 0; r < 2; r++) {
                float4 e = *(const float4*)&h1_s[rg + r][d];
                acc[r][0] = fmaf(e.x, w0.x, acc[r][0]); acc[r][1] = fmaf(e.x, w0.y, acc[r][1]);
                acc[r][0] = fmaf(e.y, w1.x, acc[r][0]); acc[r][1] = fmaf(e.y, w1.y, acc[r][1]);
                acc[r][0] = fmaf(e.z, w2.x, acc[r][0]); acc[r][1] = fmaf(e.z, w2.y, acc[r][1]);
                acc[r][0] = fmaf(e.w, w3.x, acc[r][0]); acc[r][1] = fmaf(e.w, w3.y, acc[r][1]);
            }
        }
        const float2 bb = *(const float2*)&b2[f0];
        #pragma unroll
        for (int r = 0; r < 2; r++) {
            float2 hv;
            hv.x = fmaxf(acc[r][0] + bb.x, 0.f);
            hv.y = fmaxf(acc[r][1] + bb.y, 0.f);
            *(float2*)&h2_s[rg + r][f0] = hv;
        }
    }
    __syncthreads();

    // layer 3: 64 -> 50
    {
        const int f = t & 63, rg = (t >> 6) * 4;
        if (f < 50) {
            float acc[4] = {0.f, 0.f, 0.f, 0.f};
            const float* w = W3 + f;
            #pragma unroll
            for (int d = 0; d < 64; d += 4) {
                float w0 = w[(d + 0) * 50], w1 = w[(d + 1) * 50];
                float w2 = w[(d + 2) * 50], w3 = w[(d + 3) * 50];
                #pragma unroll
                for (int r = 0; r < 4; r++) {
                    float4 e = *(const float4*)&h2_s[rg + r][d];
                    acc[r] = fmaf(e.x, w0, acc[r]); acc[r] = fmaf(e.y, w1, acc[r]);
                    acc[r] = fmaf(e.z, w2, acc[r]); acc[r] = fmaf(e.w, w3, acc[r]);
                }
            }
            const float bb = b3[f];
            #pragma unroll
            for (int r = 0; r < 4; r++) z_s[rg + r][f] = acc[r] + bb;
        }
    }
    __syncthreads();

    // bf16 split write, z scaled by sqrt(log2e) (pad K 50->64)
    {
        const int row = t >> 4, k0 = (t & 15) * 4;
        ushort4 hi4, lo4;
        unsigned short* hp = &hi4.x;
        unsigned short* lp = &lo4.x;
        #pragma unroll
        for (int j = 0; j < 4; j++) {
            const int k = k0 + j;
            float v = (k < 50) ? z_s[row][k] * SQRT_L2E : 0.f;
            bsplit(v, hp[j], lp[j]);
        }
        const size_t base = ((rowbase + row) << 6) + k0;
        *(ushort4*)(g_zhi + base) = hi4;
        *(ushort4*)(g_zlo + base) = lo4;
    }
    // scaled squared norms from UNscaled z (sequential, deterministic)
    if (t < 32) {
        float s2 = 0.f;
        #pragma unroll
        for (int k = 0; k < 50; k++) s2 = fmaf(z_s[t][k], z_s[t][k], s2);
        g_sq[rowbase + t] = NEG_HALF_L2E * s2;
    }
}

// ===========================================================================
// Kernel 2: gram — R13 per-warp structure, SINGLE B buffer -> 55.5 KB smem
// -> 3 CTAs/SM (24 warps). 32 rows x 4096, 256 threads, 32 tiles of 128.
// ===========================================================================
#define OFF_BHI  0
#define OFF_BLO  18432
#define OFF_AHI  36864
#define OFF_ALO  41472
#define OFF_NUM  46080
#define OFF_SQC  54784
#define OFF_SQR  55296
#define OFF_RSUM 55424
#define GRAM_SMEM 55552

__device__ __forceinline__ unsigned qexp(float arg) {
    float k;
    asm("ex2.approx.ftz.f32 %0, %1;" : "=f"(k) : "f"(arg));
    float p = fmaf(k, PA4, PA3);
    p = fmaf(k, p, PA2);
    p = fmaf(k, p, PA1);
    p = fmaf(k, p, PA0);
    return __float2uint_rn(p);
}

__global__ __launch_bounds__(256, 3) void gram_kernel()
{
    extern __shared__ char sm[];
    const uint32_t smu = smem_u32(sm);

    float* sqp_r = (float*)(sm + OFF_SQR);
    int*   rsum  = (int*)  (sm + OFF_RSUM);
    const float* sqp_c = (const float*)(sm + OFF_SQC);

    const int t    = threadIdx.x;
    const int lane = t & 31, warp = t >> 5;
    const int b    = blockIdx.x >> 7;
    const int r0   = (blockIdx.x & 127) * 32;
    const int gr   = lane >> 2;

    // ---- stage A + sqp_r + init rowsum ----
    {
        const int row = t >> 3, seg = t & 7;
        const size_t src = ((size_t)(b * NPTS + r0 + row) << 6) + seg * 8;
        const int dsto = (row * ASTR + seg * 8) * 2;
        *(uint4*)(sm + OFF_AHI + dsto) = *(const uint4*)(g_zhi + src);
        *(uint4*)(sm + OFF_ALO + dsto) = *(const uint4*)(g_zlo + src);
    }
    if (t < 32) { sqp_r[t] = g_sq[b * NPTS + r0 + t]; rsum[t] = 0; }

    // ---- prologue: prefetch tile 0 into the single buffer ----
    {
        #pragma unroll
        for (int i = 0; i < 4; i++) {
            const int idx = i * 256 + t;
            const int rr = idx >> 3, seg = idx & 7;
            const size_t src = ((size_t)(b * NPTS + rr) << 6) + seg * 8;
            const uint32_t dsto = (rr * BSTR + seg * 8) * 2;
            cp16(smu + OFF_BHI + dsto, g_zhi + src);
            cp16(smu + OFF_BLO + dsto, g_zlo + src);
        }
        if (t < 128) cp4(smu + OFF_SQC + t * 4, g_sq + b * NPTS + t);
        cp_commit();
    }
    __syncthreads();

    // ---- hoist A fragments (tile-invariant) ----
    const int a_lr = (lane & 7) + ((lane >> 3) & 1) * 8;
    const int a_lc = (lane >> 4) * 8;
    uint32_t afh[2][4][4], afl[2][4][4];
    #pragma unroll
    for (int ms = 0; ms < 2; ms++)
        #pragma unroll
        for (int ks = 0; ks < 4; ks++) {
            const uint32_t ao = ((ms * 16 + a_lr) * ASTR + ks * 16 + a_lc) * 2;
            ldsm_x4(smu + OFF_AHI + ao, afh[ms][ks]);
            ldsm_x4(smu + OFF_ALO + ao, afl[ms][ks]);
        }

    const int b_lr = warp * 16 + (lane & 7) + ((lane >> 4) & 1) * 8;
    const int b_lc = ((lane >> 3) & 1) * 8;

    int srow = 0;   // deferred row-sum partial (row = t>>3, tile-invariant)

    for (int tile = 0; tile < 32; tile++) {
        const int col0 = tile * 128;

        cp_wait0();
        __syncthreads();   // B tile + sqc ready

        float acc[2][2][4];
        #pragma unroll
        for (int ms = 0; ms < 2; ms++)
            #pragma unroll
            for (int ns = 0; ns < 2; ns++)
                #pragma unroll
                for (int q = 0; q < 4; q++) acc[ms][ns][q] = 0.f;

        #pragma unroll
        for (int ks = 0; ks < 4; ks++) {
            uint32_t bfh[4], bfl[4];
            const uint32_t bo = (b_lr * BSTR + ks * 16 + b_lc) * 2;
            ldsm_x4(smu + OFF_BHI + bo, bfh);
            ldsm_x4(smu + OFF_BLO + bo, bfl);
            #pragma unroll
            for (int ms = 0; ms < 2; ms++) {
                mma_bf16(acc[ms][0], afh[ms][ks], &bfh[0]);
                mma_bf16(acc[ms][1], afh[ms][ks], &bfh[2]);
                mma_bf16(acc[ms][0], afh[ms][ks], &bfl[0]);
                mma_bf16(acc[ms][1], afh[ms][ks], &bfl[2]);
                mma_bf16(acc[ms][0], afl[ms][ks], &bfh[0]);
                mma_bf16(acc[ms][1], afl[ms][ks], &bfh[2]);
            }
        }

        // ---- epilogue: arg = dot' + rr + sc (log2e pre-folded) ----
        #pragma unroll
        for (int ms = 0; ms < 2; ms++) {
            const int ra = ms * 16 + gr;
            const float rr0 = sqp_r[ra], rr1 = sqp_r[ra + 8];
            #pragma unroll
            for (int ns = 0; ns < 2; ns++) {
                const int col = warp * 16 + ns * 8 + (lane & 3) * 2;
                const float rs00 = rr0 + sqp_c[col], rs01 = rr0 + sqp_c[col + 1];
                const float rs10 = rr1 + sqp_c[col], rs11 = rr1 + sqp_c[col + 1];
                unsigned u0 = qexp(acc[ms][ns][0] + rs00);
                unsigned u1 = qexp(acc[ms][ns][1] + rs01);
                unsigned u2 = qexp(acc[ms][ns][2] + rs10);
                unsigned u3 = qexp(acc[ms][ns][3] + rs11);
                *(uint32_t*)(sm + OFF_NUM + (ra * NSTR + col) * 2)       = u0 | (u1 << 16);
                *(uint32_t*)(sm + OFF_NUM + ((ra + 8) * NSTR + col) * 2) = u2 | (u3 << 16);
            }
        }
        __syncthreads();   // NUM staged; all mma/epilogue reads of B+sqc done

        // ---- issue next tile's loads into the (now free) single buffer ----
        if (tile < 31) {
            #pragma unroll
            for (int i = 0; i < 4; i++) {
                const int idx = i * 256 + t;
                const int rr = idx >> 3, seg = idx & 7;
                const size_t src = ((size_t)(b * NPTS + col0 + 128 + rr) << 6) + seg * 8;
                const uint32_t dsto = (rr * BSTR + seg * 8) * 2;
                cp16(smu + OFF_BHI + dsto, g_zhi + src);
                cp16(smu + OFF_BLO + dsto, g_zlo + src);
            }
            if (t < 128) cp4(smu + OFF_SQC + t * 4, g_sq + b * NPTS + col0 + 128 + t);
        }
        cp_commit();

        // ---- copy-out; accumulate row partial in register (deferred) ----
        {
            const int row = t >> 3, cbase = (t & 7) * 16;
            unsigned short* gdst = g_num +
                ((size_t)(b * NPTS + r0 + row) << 12) + col0 + cbase;
            #pragma unroll
            for (int j = 0; j < 2; j++) {
                uint4 v = *(const uint4*)(sm + OFF_NUM + (row * NSTR + cbase + j * 8) * 2);
                srow += (int)(v.x & 0xFFFFu) + (int)(v.x >> 16);
                srow += (int)(v.y & 0xFFFFu) + (int)(v.y >> 16);
                srow += (int)(v.z & 0xFFFFu) + (int)(v.z >> 16);
                srow += (int)(v.w & 0xFFFFu) + (int)(v.w >> 16);
                *(uint4*)(gdst + j * 8) = v;
            }
        }
    }

    // ---- deferred row-sum reduce: 8 lanes per row -> one atomic each ----
    srow += __shfl_xor_sync(0xFFFFFFFFu, srow, 1);
    srow += __shfl_xor_sync(0xFFFFFFFFu, srow, 2);
    srow += __shfl_xor_sync(0xFFFFFFFFu, srow, 4);
    if ((lane & 7) == 0) atomicAdd(&rsum[t >> 3], srow);
    __syncthreads();

    if (t < 32)
        g_scale[b * NPTS + r0 + t] = INV_RENORM / (float)rsum[t];
}

// ===========================================================================
// Kernel 3: rescale u16 numerators -> float output.
// 512 threads, 2 independent uint4 per thread, grid 8192.
// ===========================================================================
__global__ __launch_bounds__(512) void rescale_kernel(float* __restrict__ out)
{
    const float bias = 1e-6f * INV_RENORM;
    const size_t base = (size_t)blockIdx.x * 1024 + threadIdx.x;
    #pragma unroll
    for (int h = 0; h < 2; h++) {
        const size_t idx = base + h * 512;
        const size_t row = idx >> 9;
        const uint4 v = ((const uint4*)g_num)[idx];
        const float s = g_scale[row];
        float4 o0, o1;
        o0.x = fmaf((float)(v.x & 0xFFFFu), s, bias);
        o0.y = fmaf((float)(v.x >> 16),     s, bias);
        o0.z = fmaf((float)(v.y & 0xFFFFu), s, bias);
        o0.w = fmaf((float)(v.y >> 16),     s, bias);
        o1.x = fmaf((float)(v.z & 0xFFFFu), s, bias);
        o1.y = fmaf((float)(v.z >> 16),     s, bias);
        o1.z = fmaf((float)(v.w & 0xFFFFu), s, bias);
        o1.w = fmaf((float)(v.w >> 16),     s, bias);
        ((float4*)out)[idx * 2]     = o0;
        ((float4*)out)[idx * 2 + 1] = o1;
    }
}

// ===========================================================================
extern "C" void kernel_launch(void* const* d_in, const int* in_sizes, int n_in,
                              void* d_out, int out_size)
{
    const float* emb = (const float*)d_in[0];
    const float* W1  = (const float*)d_in[1];
    const float* b1  = (const float*)d_in[2];
    const float* W2  = (const float*)d_in[3];
    const float* b2  = (const float*)d_in[4];
    const float* W3  = (const float*)d_in[5];
    const float* b3  = (const float*)d_in[6];
    float* out = (float*)d_out;

    cudaFuncSetAttribute(mlp_kernel,  cudaFuncAttributeMaxDynamicSharedMemorySize, MLP_SMEM);
    cudaFuncSetAttribute(gram_kernel, cudaFuncAttributeMaxDynamicSharedMemorySize, GRAM_SMEM);

    mlp_kernel<<<512, 512, MLP_SMEM>>>(emb, W1, b1, W2, b2, W3, b3);
    gram_kernel<<<512, 256, GRAM_SMEM>>>();
    rescale_kernel<<<8192, 512>>>(out);
}

// round 16
// speedup vs baseline: 1.2624x; 1.2624x over previous
#include <cuda_runtime.h>
#include <cuda_bf16.h>
#include <cstdint>

#define NPTS 4096
#define NROWS_TOT 16384
#define INV_RENORM (1.0f / 1.004096f)
#define NEG_HALF_L2E (-0.72134752f)
#define SQRT_L2E 1.2011224087f

// degree-4 poly of 24000*exp(x) on [0,1], abs err ~1 count
#define PA0 24000.62f
#define PA1 23969.11f
#define PA2 12239.55f
#define PA3 3359.48f
#define PA4 1669.28f

#define ASTR 72
#define BSTR 72
#define NSTR 136

// ---- device-global scratch ----
__device__ __align__(16) unsigned short g_zhi[NROWS_TOT * 64];
__device__ __align__(16) unsigned short g_zlo[NROWS_TOT * 64];
__device__ __align__(16) float          g_sq [NROWS_TOT];      // -log2e/2 * ||z||^2
__device__ __align__(16) unsigned short g_num[(size_t)NROWS_TOT * NPTS];
__device__ __align__(16) float          g_scale[NROWS_TOT];

// ---- PTX helpers ----
__device__ __forceinline__ void ldsm_x4(uint32_t addr, uint32_t* r) {
    asm volatile("ldmatrix.sync.aligned.m8n8.x4.shared.b16 {%0,%1,%2,%3}, [%4];"
                 : "=r"(r[0]), "=r"(r[1]), "=r"(r[2]), "=r"(r[3]) : "r"(addr));
}
__device__ __forceinline__ void mma_bf16(float* d, const uint32_t* a, const uint32_t* b) {
    asm volatile(
        "mma.sync.aligned.m16n8k16.row.col.f32.bf16.bf16.f32 "
        "{%0,%1,%2,%3},{%4,%5,%6,%7},{%8,%9},{%0,%1,%2,%3};"
        : "+f"(d[0]), "+f"(d[1]), "+f"(d[2]), "+f"(d[3])
        : "r"(a[0]), "r"(a[1]), "r"(a[2]), "r"(a[3]), "r"(b[0]), "r"(b[1]));
}
__device__ __forceinline__ void cp16(uint32_t dst, const void* src) {
    asm volatile("cp.async.cg.shared.global [%0], [%1], 16;" :: "r"(dst), "l"(src));
}
__device__ __forceinline__ void cp4(uint32_t dst, const void* src) {
    asm volatile("cp.async.ca.shared.global [%0], [%1], 4;" :: "r"(dst), "l"(src));
}
__device__ __forceinline__ void cp_commit() { asm volatile("cp.async.commit_group;"); }
__device__ __forceinline__ void cp_wait1()  { asm volatile("cp.async.wait_group 1;"); }

__device__ __forceinline__ void bsplit(float v, unsigned short& h, unsigned short& l) {
    __nv_bfloat16 hh = __float2bfloat16(v);
    float hf = __bfloat162float(hh);
    __nv_bfloat16 ll = __float2bfloat16(v - hf);
    h = __bfloat16_as_ushort(hh);
    l = __bfloat16_as_ushort(ll);
}
__device__ __forceinline__ uint32_t smem_u32(const void* p) {
    uint32_t a;
    asm("{ .reg .u64 tt; cvta.to.shared.u64 tt, %1; cvt.u32.u64 %0, tt; }" : "=r"(a) : "l"(p));
    return a;
}

// ===========================================================================
// Kernel 1: MLP 256 -> 128 -> 64 -> 50, f-blocked x2 (R8/R11/R13-proven).
// 32 rows/CTA, 512 threads, grid 512, layer-1 unroll 2.
// ===========================================================================
#define MLP_SMEM 64000

__global__ __launch_bounds__(512) void mlp_kernel(
    const float* __restrict__ emb,
    const float* __restrict__ W1, const float* __restrict__ b1,
    const float* __restrict__ W2, const float* __restrict__ b2,
    const float* __restrict__ W3, const float* __restrict__ b3)
{
    extern __shared__ char msm[];
    float (*E_s)[256]  = (float(*)[256])(msm);
    float (*h1_s)[128] = (float(*)[128])(msm + 32768);
    float (*h2_s)[64]  = (float(*)[64]) (msm + 49152);
    float (*z_s)[52]   = (float(*)[52]) (msm + 57344);

    const int t = threadIdx.x;
    const size_t rowbase = (size_t)blockIdx.x * 32;

    {
        const float4* src = (const float4*)(emb + rowbase * 256);
        float4* dst = (float4*)&E_s[0][0];
        #pragma unroll
        for (int i = 0; i < 4; i++) dst[t + i * 512] = src[t + i * 512];
    }
    __syncthreads();

    // layer 1: 256 -> 128, relu.  f-pair = (t&63)*2, rows (t>>6)*4..+3
    {
        const int f0 = (t & 63) * 2, rg = (t >> 6) * 4;
        float acc[4][2];
        #pragma unroll
        for (int r = 0; r < 4; r++) { acc[r][0] = 0.f; acc[r][1] = 0.f; }
        const float* w = W1 + f0;
        #pragma unroll 2
        for (int d = 0; d < 256; d += 4) {
            float2 w0 = *(const float2*)&w[(d + 0) * 128];
            float2 w1 = *(const float2*)&w[(d + 1) * 128];
            float2 w2 = *(const float2*)&w[(d + 2) * 128];
            float2 w3 = *(const float2*)&w[(d + 3) * 128];
            #pragma unroll
            for (int r = 0; r < 4; r++) {
                float4 e = *(const float4*)&E_s[rg + r][d];
                acc[r][0] = fmaf(e.x, w0.x, acc[r][0]); acc[r][1] = fmaf(e.x, w0.y, acc[r][1]);
                acc[r][0] = fmaf(e.y, w1.x, acc[r][0]); acc[r][1] = fmaf(e.y, w1.y, acc[r][1]);
                acc[r][0] = fmaf(e.z, w2.x, acc[r][0]); acc[r][1] = fmaf(e.z, w2.y, acc[r][1]);
                acc[r][0] = fmaf(e.w, w3.x, acc[r][0]); acc[r][1] = fmaf(e.w, w3.y, acc[r][1]);
            }
        }
        const float2 bb = *(const float2*)&b1[f0];
        #pragma unroll
        for (int r = 0; r < 4; r++) {
            float2 hv;
            hv.x = fmaxf(acc[r][0] + bb.x, 0.f);
            hv.y = fmaxf(acc[r][1] + bb.y, 0.f);
            *(float2*)&h1_s[rg + r][f0] = hv;
        }
    }
    __syncthreads();

    // layer 2: 128 -> 64, relu
    {
        const int f0 = (t & 31) * 2, rg = (t >> 5) * 2;
        float acc[2][2];
        acc[0][0] = acc[0][1] = acc[1][0] = acc[1][1] = 0.f;
        const float* w = W2 + f0;
        #pragma unroll 2
        for (int d = 0; d < 128; d += 4) {
            float2 w0 = *(const float2*)&w[(d + 0) * 64];
            float2 w1 = *(const float2*)&w[(d + 1) * 64];
            float2 w2 = *(const float2*)&w[(d + 2) * 64];
            float2 w3 = *(const float2*)&w[(d + 3) * 64];
            #pragma unroll
            for (int r = 0; r < 2; r++) {
                float4 e = *(const float4*)&h1_s[rg + r][d];
                acc[r][0] = fmaf(e.x, w0.x, acc[r][0]); acc[r][1] = fmaf(e.x, w0.y, acc[r][1]);
                acc[r][0] = fmaf(e.y, w1.x, acc[r][0]); acc[r][1] = fmaf(e.y, w1.y, acc[r][1]);
                acc[r][0] = fmaf(e.z, w2.x, acc[r][0]); acc[r][1] = fmaf(e.z, w2.y, acc[r][1]);
                acc[r][0] = fmaf(e.w, w3.x, acc[r][0]); acc[r][1] = fmaf(e.w, w3.y, acc[r][1]);
            }
        }
        const float2 bb = *(const float2*)&b2[f0];
        #pragma unroll
        for (int r = 0; r < 2; r++) {
            float2 hv;
            hv.x = fmaxf(acc[r][0] + bb.x, 0.f);
            hv.y = fmaxf(acc[r][1] + bb.y, 0.f);
            *(float2*)&h2_s[rg + r][f0] = hv;
        }
    }
    __syncthreads();

    // layer 3: 64 -> 50
    {
        const int f = t & 63, rg = (t >> 6) * 4;
        if (f < 50) {
            float acc[4] = {0.f, 0.f, 0.f, 0.f};
            const float* w = W3 + f;
            #pragma unroll
            for (int d = 0; d < 64; d += 4) {
                float w0 = w[(d + 0) * 50], w1 = w[(d + 1) * 50];
                float w2 = w[(d + 2) * 50], w3 = w[(d + 3) * 50];
                #pragma unroll
                for (int r = 0; r < 4; r++) {
                    float4 e = *(const float4*)&h2_s[rg + r][d];
                    acc[r] = fmaf(e.x, w0, acc[r]); acc[r] = fmaf(e.y, w1, acc[r]);
                    acc[r] = fmaf(e.z, w2, acc[r]); acc[r] = fmaf(e.w, w3, acc[r]);
                }
            }
            const float bb = b3[f];
            #pragma unroll
            for (int r = 0; r < 4; r++) z_s[rg + r][f] = acc[r] + bb;
        }
    }
    __syncthreads();

    // bf16 split write, z scaled by sqrt(log2e) (pad K 50->64)
    {
        const int row = t >> 4, k0 = (t & 15) * 4;
        ushort4 hi4, lo4;
        unsigned short* hp = &hi4.x;
        unsigned short* lp = &lo4.x;
        #pragma unroll
        for (int j = 0; j < 4; j++) {
            const int k = k0 + j;
            float v = (k < 50) ? z_s[row][k] * SQRT_L2E : 0.f;
            bsplit(v, hp[j], lp[j]);
        }
        const size_t base = ((rowbase + row) << 6) + k0;
        *(ushort4*)(g_zhi + base) = hi4;
        *(ushort4*)(g_zlo + base) = lo4;
    }
    // scaled squared norms from UNscaled z (sequential, deterministic)
    if (t < 32) {
        float s2 = 0.f;
        #pragma unroll
        for (int k = 0; k < 50; k++) s2 = fmaf(z_s[t][k], z_s[t][k], s2);
        g_sq[rowbase + t] = NEG_HALF_L2E * s2;
    }
}

// ===========================================================================
// Kernel 2: gram (R13-proven shape). Delta: ALL B fragments for the tile
// loaded into registers up front, then the 48-mma chain runs uninterrupted.
// CTA = 32 rows x 4096 cols, 256 threads, 32 tiles of 128, double-buffered.
// smem 92,928 B -> 2 CTAs/SM.
// ===========================================================================
#define OFF_B    0
#define BUF_SZ   36864
#define BLO_OFF  18432
#define OFF_AHI  73728
#define OFF_ALO  78336
#define OFF_NUM  82944
#define OFF_SQC  91648
#define OFF_SQR  92672
#define OFF_RSUM 92800
#define GRAM_SMEM 92928

__device__ __forceinline__ unsigned qexp(float arg) {
    float k;
    asm("ex2.approx.ftz.f32 %0, %1;" : "=f"(k) : "f"(arg));
    float p = fmaf(k, PA4, PA3);
    p = fmaf(k, p, PA2);
    p = fmaf(k, p, PA1);
    p = fmaf(k, p, PA0);
    return __float2uint_rn(p);
}

__global__ __launch_bounds__(256, 2) void gram_kernel()
{
    extern __shared__ char sm[];
    const uint32_t smu = smem_u32(sm);

    float* sqp_r = (float*)(sm + OFF_SQR);
    int*   rsum  = (int*)  (sm + OFF_RSUM);

    const int t    = threadIdx.x;
    const int lane = t & 31, warp = t >> 5;
    const int b    = blockIdx.x >> 7;
    const int r0   = (blockIdx.x & 127) * 32;
    const int gr   = lane >> 2;

    // ---- stage A + sqp_r + init rowsum ----
    {
        const int row = t >> 3, seg = t & 7;
        const size_t src = ((size_t)(b * NPTS + r0 + row) << 6) + seg * 8;
        const int dsto = (row * ASTR + seg * 8) * 2;
        *(uint4*)(sm + OFF_AHI + dsto) = *(const uint4*)(g_zhi + src);
        *(uint4*)(sm + OFF_ALO + dsto) = *(const uint4*)(g_zlo + src);
    }
    if (t < 32) { sqp_r[t] = g_sq[b * NPTS + r0 + t]; rsum[t] = 0; }

    // ---- prologue: prefetch tiles 0 and 1 ----
    #pragma unroll
    for (int pt = 0; pt < 2; pt++) {
        const uint32_t bbase = smu + OFF_B + pt * BUF_SZ;
        #pragma unroll
        for (int i = 0; i < 4; i++) {
            const int idx = i * 256 + t;
            const int rr = idx >> 3, seg = idx & 7;
            const size_t src = ((size_t)(b * NPTS + pt * 128 + rr) << 6) + seg * 8;
            const uint32_t dsto = (rr * BSTR + seg * 8) * 2;
            cp16(bbase + dsto, g_zhi + src);
            cp16(bbase + BLO_OFF + dsto, g_zlo + src);
        }
        if (t < 128) cp4(smu + OFF_SQC + pt * 512 + t * 4, g_sq + b * NPTS + pt * 128 + t);
        cp_commit();
    }
    __syncthreads();

    // ---- hoist A fragments (tile-invariant) ----
    const int a_lr = (lane & 7) + ((lane >> 3) & 1) * 8;
    const int a_lc = (lane >> 4) * 8;
    uint32_t afh[2][4][4], afl[2][4][4];
    #pragma unroll
    for (int ms = 0; ms < 2; ms++)
        #pragma unroll
        for (int ks = 0; ks < 4; ks++) {
            const uint32_t ao = ((ms * 16 + a_lr) * ASTR + ks * 16 + a_lc) * 2;
            ldsm_x4(smu + OFF_AHI + ao, afh[ms][ks]);
            ldsm_x4(smu + OFF_ALO + ao, afl[ms][ks]);
        }

    const int b_lr = warp * 16 + (lane & 7) + ((lane >> 4) & 1) * 8;
    const int b_lc = ((lane >> 3) & 1) * 8;

    int srow = 0;   // deferred row-sum partial (row = t>>3, tile-invariant)

    for (int tile = 0; tile < 32; tile++) {
        const int col0 = tile * 128;
        const int buf  = tile & 1;
        const uint32_t bbase = smu + OFF_B + buf * BUF_SZ;
        const float* sqp_c = (const float*)(sm + OFF_SQC + buf * 512);

        cp_wait1();
        __syncthreads();

        // ---- load ALL B fragments for this tile up front (8 ldsm) ----
        uint32_t bfh[4][4], bfl[4][4];
        #pragma unroll
        for (int ks = 0; ks < 4; ks++) {
            const uint32_t bo = (b_lr * BSTR + ks * 16 + b_lc) * 2;
            ldsm_x4(bbase + bo, bfh[ks]);
            ldsm_x4(bbase + BLO_OFF + bo, bfl[ks]);
        }

        // ---- uninterrupted 48-mma chain ----
        float acc[2][2][4];
        #pragma unroll
        for (int ms = 0; ms < 2; ms++)
            #pragma unroll
            for (int ns = 0; ns < 2; ns++)
                #pragma unroll
                for (int q = 0; q < 4; q++) acc[ms][ns][q] = 0.f;

        #pragma unroll
        for (int ks = 0; ks < 4; ks++) {
            #pragma unroll
            for (int ms = 0; ms < 2; ms++) {
                mma_bf16(acc[ms][0], afh[ms][ks], &bfh[ks][0]);
                mma_bf16(acc[ms][1], afh[ms][ks], &bfh[ks][2]);
                mma_bf16(acc[ms][0], afh[ms][ks], &bfl[ks][0]);
                mma_bf16(acc[ms][1], afh[ms][ks], &bfl[ks][2]);
                mma_bf16(acc[ms][0], afl[ms][ks], &bfh[ks][0]);
                mma_bf16(acc[ms][1], afl[ms][ks], &bfh[ks][2]);
            }
        }

        // ---- epilogue: arg = dot' + rr + sc (log2e pre-folded) ----
        #pragma unroll
        for (int ms = 0; ms < 2; ms++) {
            const int ra = ms * 16 + gr;
            const float rr0 = sqp_r[ra], rr1 = sqp_r[ra + 8];
            #pragma unroll
            for (int ns = 0; ns < 2; ns++) {
                const int col = warp * 16 + ns * 8 + (lane & 3) * 2;
                const float rs00 = rr0 + sqp_c[col], rs01 = rr0 + sqp_c[col + 1];
                const float rs10 = rr1 + sqp_c[col], rs11 = rr1 + sqp_c[col + 1];
                unsigned u0 = qexp(acc[ms][ns][0] + rs00);
                unsigned u1 = qexp(acc[ms][ns][1] + rs01);
                unsigned u2 = qexp(acc[ms][ns][2] + rs10);
                unsigned u3 = qexp(acc[ms][ns][3] + rs11);
                *(uint32_t*)(sm + OFF_NUM + (ra * NSTR + col) * 2)       = u0 | (u1 << 16);
                *(uint32_t*)(sm + OFF_NUM + ((ra + 8) * NSTR + col) * 2) = u2 | (u3 << 16);
            }
        }
        __syncthreads();

        // ---- prefetch tile+2 ----
        if (tile < 30) {
            #pragma unroll
            for (int i = 0; i < 4; i++) {
                const int idx = i * 256 + t;
                const int rr = idx >> 3, seg = idx & 7;
                const size_t src = ((size_t)(b * NPTS + col0 + 256 + rr) << 6) + seg * 8;
                const uint32_t dsto = (rr * BSTR + seg * 8) * 2;
                cp16(bbase + dsto, g_zhi + src);
                cp16(bbase + BLO_OFF + dsto, g_zlo + src);
            }
            if (t < 128) cp4(smu + OFF_SQC + buf * 512 + t * 4,
                             g_sq + b * NPTS + col0 + 256 + t);
        }
        cp_commit();

        // ---- copy-out; accumulate row partial in register (deferred) ----
        {
            const int row = t >> 3, cbase = (t & 7) * 16;
            unsigned short* gdst = g_num +
                ((size_t)(b * NPTS + r0 + row) << 12) + col0 + cbase;
            #pragma unroll
            for (int j = 0; j < 2; j++) {
                uint4 v = *(const uint4*)(sm + OFF_NUM + (row * NSTR + cbase + j * 8) * 2);
                srow += (int)(v.x & 0xFFFFu) + (int)(v.x >> 16);
                srow += (int)(v.y & 0xFFFFu) + (int)(v.y >> 16);
                srow += (int)(v.z & 0xFFFFu) + (int)(v.z >> 16);
                srow += (int)(v.w & 0xFFFFu) + (int)(v.w >> 16);
                *(uint4*)(gdst + j * 8) = v;
            }
        }
    }

    // ---- deferred row-sum reduce: 8 lanes per row -> one atomic each ----
    srow += __shfl_xor_sync(0xFFFFFFFFu, srow, 1);
    srow += __shfl_xor_sync(0xFFFFFFFFu, srow, 2);
    srow += __shfl_xor_sync(0xFFFFFFFFu, srow, 4);
    if ((lane & 7) == 0) atomicAdd(&rsum[t >> 3], srow);
    __syncthreads();

    if (t < 32)
        g_scale[b * NPTS + r0 + t] = INV_RENORM / (float)rsum[t];
}

// ===========================================================================
// Kernel 3: rescale u16 numerators -> float output.
// 512 threads, 2 independent uint4 per thread, grid 8192.
// ===========================================================================
__global__ __launch_bounds__(512) void rescale_kernel(float* __restrict__ out)
{
    const float bias = 1e-6f * INV_RENORM;
    const size_t base = (size_t)blockIdx.x * 1024 + threadIdx.x;
    #pragma unroll
    for (int h = 0; h < 2; h++) {
        const size_t idx = base + h * 512;
        const size_t row = idx >> 9;
        const uint4 v = ((const uint4*)g_num)[idx];
        const float s = g_scale[row];
        float4 o0, o1;
        o0.x = fmaf((float)(v.x & 0xFFFFu), s, bias);
        o0.y = fmaf((float)(v.x >> 16),     s, bias);
        o0.z = fmaf((float)(v.y & 0xFFFFu), s, bias);
        o0.w = fmaf((float)(v.y >> 16),     s, bias);
        o1.x = fmaf((float)(v.z & 0xFFFFu), s, bias);
        o1.y = fmaf((float)(v.z >> 16),     s, bias);
        o1.z = fmaf((float)(v.w & 0xFFFFu), s, bias);
        o1.w = fmaf((float)(v.w >> 16),     s, bias);
        ((float4*)out)[idx * 2]     = o0;
        ((float4*)out)[idx * 2 + 1] = o1;
    }
}

// ===========================================================================
extern "C" void kernel_launch(void* const* d_in, const int* in_sizes, int n_in,
                              void* d_out, int out_size)
{
    const float* emb = (const float*)d_in[0];
    const float* W1  = (const float*)d_in[1];
    const float* b1  = (const float*)d_in[2];
    const float* W2  = (const float*)d_in[3];
    const float* b2  = (const float*)d_in[4];
    const float* W3  = (const float*)d_in[5];
    const float* b3  = (const float*)d_in[6];
    float* out = (float*)d_out;

    cudaFuncSetAttribute(mlp_kernel,  cudaFuncAttributeMaxDynamicSharedMemorySize, MLP_SMEM);
    cudaFuncSetAttribute(gram_kernel, cudaFuncAttributeMaxDynamicSharedMemorySize, GRAM_SMEM);

    mlp_kernel<<<512, 512, MLP_SMEM>>>(emb, W1, b1, W2, b2, W3, b3);
    gram_kernel<<<512, 256, GRAM_SMEM>>>();
    rescale_kernel<<<8192, 512>>>(out);
}

// round 17
// speedup vs baseline: 1.3683x; 1.0838x over previous
#include <cuda_runtime.h>
#include <cuda_bf16.h>
#include <cstdint>

#define NPTS 4096
#define NROWS_TOT 16384
#define INV_RENORM (1.0f / 1.004096f)
#define NEG_HALF_L2E (-0.72134752f)
#define SQRT_L2E 1.2011224087f

// degree-4 poly of 24000*exp(x) on [0,1], abs err ~1 count
#define PA0 24000.62f
#define PA1 23969.11f
#define PA2 12239.55f
#define PA3 3359.48f
#define PA4 1669.28f

#define ASTR 72
#define BSTR 72
#define NSTR 136

// ---- device-global scratch ----
__device__ __align__(16) unsigned short g_zhi[NROWS_TOT * 64];
__device__ __align__(16) unsigned short g_zlo[NROWS_TOT * 64];
__device__ __align__(16) float          g_sq [NROWS_TOT];      // -log2e/2 * ||z||^2
__device__ __align__(16) unsigned short g_num[(size_t)NROWS_TOT * NPTS];
__device__ __align__(16) float          g_scale[NROWS_TOT];

// ---- PTX helpers ----
__device__ __forceinline__ void ldsm_x4(uint32_t addr, uint32_t* r) {
    asm volatile("ldmatrix.sync.aligned.m8n8.x4.shared.b16 {%0,%1,%2,%3}, [%4];"
                 : "=r"(r[0]), "=r"(r[1]), "=r"(r[2]), "=r"(r[3]) : "r"(addr));
}
__device__ __forceinline__ void mma_bf16(float* d, const uint32_t* a, const uint32_t* b) {
    asm volatile(
        "mma.sync.aligned.m16n8k16.row.col.f32.bf16.bf16.f32 "
        "{%0,%1,%2,%3},{%4,%5,%6,%7},{%8,%9},{%0,%1,%2,%3};"
        : "+f"(d[0]), "+f"(d[1]), "+f"(d[2]), "+f"(d[3])
        : "r"(a[0]), "r"(a[1]), "r"(a[2]), "r"(a[3]), "r"(b[0]), "r"(b[1]));
}
__device__ __forceinline__ void cp16(uint32_t dst, const void* src) {
    asm volatile("cp.async.cg.shared.global [%0], [%1], 16;" :: "r"(dst), "l"(src));
}
__device__ __forceinline__ void cp4(uint32_t dst, const void* src) {
    asm volatile("cp.async.ca.shared.global [%0], [%1], 4;" :: "r"(dst), "l"(src));
}
__device__ __forceinline__ void cp_commit() { asm volatile("cp.async.commit_group;"); }
__device__ __forceinline__ void cp_wait1()  { asm volatile("cp.async.wait_group 1;"); }

__device__ __forceinline__ void bsplit(float v, unsigned short& h, unsigned short& l) {
    __nv_bfloat16 hh = __float2bfloat16(v);
    float hf = __bfloat162float(hh);
    __nv_bfloat16 ll = __float2bfloat16(v - hf);
    h = __bfloat16_as_ushort(hh);
    l = __bfloat16_as_ushort(ll);
}
__device__ __forceinline__ uint32_t smem_u32(const void* p) {
    uint32_t a;
    asm("{ .reg .u64 tt; cvta.to.shared.u64 tt, %1; cvt.u32.u64 %0, tt; }" : "=r"(a) : "l"(p));
    return a;
}

// ===========================================================================
// Kernel 1: MLP 256 -> 128 -> 64 -> 50.  Layer-1 weights streamed through
// smem via cp.async double-buffer (gram-style pipeline); W read as LDS.64.
// 32 rows/CTA, 512 threads, grid 512.
// smem: E_s @0 (32K) | Wbuf[2][16][128]f @32768 (16K) | h1_s @49152 (16K)
//       after layer1: h2_s @0, z_s @8192 (overlay E_s)
// ===========================================================================
#define MLP_SMEM 65536
#define MOFF_W 32768
#define MOFF_H1 49152

__global__ __launch_bounds__(512) void mlp_kernel(
    const float* __restrict__ emb,
    const float* __restrict__ W1, const float* __restrict__ b1,
    const float* __restrict__ W2, const float* __restrict__ b2,
    const float* __restrict__ W3, const float* __restrict__ b3)
{
    extern __shared__ char msm[];
    const uint32_t smu = smem_u32(msm);
    float (*E_s)[256]  = (float(*)[256])(msm);
    float (*h1_s)[128] = (float(*)[128])(msm + MOFF_H1);
    float (*h2_s)[64]  = (float(*)[64]) (msm);           // overlay E_s after L1
    float (*z_s)[52]   = (float(*)[52]) (msm + 8192);    // overlay E_s after L1

    const int t = threadIdx.x;
    const size_t rowbase = (size_t)blockIdx.x * 32;

    // stage E (32x256 f32)
    {
        const float4* src = (const float4*)(emb + rowbase * 256);
        float4* dst = (float4*)&E_s[0][0];
        #pragma unroll
        for (int i = 0; i < 4; i++) dst[t + i * 512] = src[t + i * 512];
    }
    // prefetch W1 chunks 0,1 (each 16 d-rows = 8192 B contiguous)
    #pragma unroll
    for (int pc = 0; pc < 2; pc++) {
        cp16(smu + MOFF_W + pc * 8192 + t * 16, (const char*)W1 + pc * 8192 + t * 16);
        cp_commit();
    }
    __syncthreads();

    // ---- layer 1: 256 -> 128, relu.  W from smem pipeline ----
    {
        const int f0 = (t & 63) * 2, rg = (t >> 6) * 4;
        float acc[4][2];
        #pragma unroll
        for (int r = 0; r < 4; r++) { acc[r][0] = 0.f; acc[r][1] = 0.f; }

        for (int c = 0; c < 16; c++) {
            cp_wait1();
            __syncthreads();        // chunk c ready; prev chunk reads done
            const float* wb = (const float*)(msm + MOFF_W + (c & 1) * 8192) + f0;
            #pragma unroll
            for (int dd = 0; dd < 16; dd += 4) {
                float2 w0 = *(const float2*)&wb[(dd + 0) * 128];
                float2 w1 = *(const float2*)&wb[(dd + 1) * 128];
                float2 w2 = *(const float2*)&wb[(dd + 2) * 128];
                float2 w3 = *(const float2*)&wb[(dd + 3) * 128];
                #pragma unroll
                for (int r = 0; r < 4; r++) {
                    float4 e = *(const float4*)&E_s[rg + r][c * 16 + dd];
                    acc[r][0] = fmaf(e.x, w0.x, acc[r][0]); acc[r][1] = fmaf(e.x, w0.y, acc[r][1]);
                    acc[r][0] = fmaf(e.y, w1.x, acc[r][0]); acc[r][1] = fmaf(e.y, w1.y, acc[r][1]);
                    acc[r][0] = fmaf(e.z, w2.x, acc[r][0]); acc[r][1] = fmaf(e.z, w2.y, acc[r][1]);
                    acc[r][0] = fmaf(e.w, w3.x, acc[r][0]); acc[r][1] = fmaf(e.w, w3.y, acc[r][1]);
                }
            }
            __syncthreads();        // all reads of buffer (c&1) done
            if (c < 14)
                cp16(smu + MOFF_W + (c & 1) * 8192 + t * 16,
                     (const char*)W1 + (c + 2) * 8192 + t * 16);
            cp_commit();            // commit every iter (FIFO push, gram-proven)
        }

        const float2 bb = *(const float2*)&b1[f0];
        #pragma unroll
        for (int r = 0; r < 4; r++) {
            float2 hv;
            hv.x = fmaxf(acc[r][0] + bb.x, 0.f);
            hv.y = fmaxf(acc[r][1] + bb.y, 0.f);
            *(float2*)&h1_s[rg + r][f0] = hv;
        }
    }
    __syncthreads();

    // ---- layer 2: 128 -> 64, relu (h2 overlays E_s; E reads all done) ----
    {
        const int f0 = (t & 31) * 2, rg = (t >> 5) * 2;
        float acc[2][2];
        acc[0][0] = acc[0][1] = acc[1][0] = acc[1][1] = 0.f;
        const float* w = W2 + f0;
        #pragma unroll 2
        for (int d = 0; d < 128; d += 4) {
            float2 w0 = *(const float2*)&w[(d + 0) * 64];
            float2 w1 = *(const float2*)&w[(d + 1) * 64];
            float2 w2 = *(const float2*)&w[(d + 2) * 64];
            float2 w3 = *(const float2*)&w[(d + 3) * 64];
            #pragma unroll
            for (int r = 0; r < 2; r++) {
                float4 e = *(const float4*)&h1_s[rg + r][d];
                acc[r][0] = fmaf(e.x, w0.x, acc[r][0]); acc[r][1] = fmaf(e.x, w0.y, acc[r][1]);
                acc[r][0] = fmaf(e.y, w1.x, acc[r][0]); acc[r][1] = fmaf(e.y, w1.y, acc[r][1]);
                acc[r][0] = fmaf(e.z, w2.x, acc[r][0]); acc[r][1] = fmaf(e.z, w2.y, acc[r][1]);
                acc[r][0] = fmaf(e.w, w3.x, acc[r][0]); acc[r][1] = fmaf(e.w, w3.y, acc[r][1]);
            }
        }
        const float2 bb = *(const float2*)&b2[f0];
        #pragma unroll
        for (int r = 0; r < 2; r++) {
            float2 hv;
            hv.x = fmaxf(acc[r][0] + bb.x, 0.f);
            hv.y = fmaxf(acc[r][1] + bb.y, 0.f);
            *(float2*)&h2_s[rg + r][f0] = hv;
        }
    }
    __syncthreads();

    // ---- layer 3: 64 -> 50 ----
    {
        const int f = t & 63, rg = (t >> 6) * 4;
        if (f < 50) {
            float acc[4] = {0.f, 0.f, 0.f, 0.f};
            const float* w = W3 + f;
            #pragma unroll
            for (int d = 0; d < 64; d += 4) {
                float w0 = w[(d + 0) * 50], w1 = w[(d + 1) * 50];
                float w2 = w[(d + 2) * 50], w3 = w[(d + 3) * 50];
                #pragma unroll
                for (int r = 0; r < 4; r++) {
                    float4 e = *(const float4*)&h2_s[rg + r][d];
                    acc[r] = fmaf(e.x, w0, acc[r]); acc[r] = fmaf(e.y, w1, acc[r]);
                    acc[r] = fmaf(e.z, w2, acc[r]); acc[r] = fmaf(e.w, w3, acc[r]);
                }
            }
            const float bb = b3[f];
            #pragma unroll
            for (int r = 0; r < 4; r++) z_s[rg + r][f] = acc[r] + bb;
        }
    }
    __syncthreads();

    // ---- bf16 split write, z scaled by sqrt(log2e) (pad K 50->64) ----
    {
        const int row = t >> 4, k0 = (t & 15) * 4;
        ushort4 hi4, lo4;
        unsigned short* hp = &hi4.x;
        unsigned short* lp = &lo4.x;
        #pragma unroll
        for (int j = 0; j < 4; j++) {
            const int k = k0 + j;
            float v = (k < 50) ? z_s[row][k] * SQRT_L2E : 0.f;
            bsplit(v, hp[j], lp[j]);
        }
        const size_t base = ((rowbase + row) << 6) + k0;
        *(ushort4*)(g_zhi + base) = hi4;
        *(ushort4*)(g_zlo + base) = lo4;
    }
    // scaled squared norms from UNscaled z (sequential, deterministic)
    if (t < 32) {
        float s2 = 0.f;
        #pragma unroll
        for (int k = 0; k < 50; k++) s2 = fmaf(z_s[t][k], z_s[t][k], s2);
        g_sq[rowbase + t] = NEG_HALF_L2E * s2;
    }
}

// ===========================================================================
// Kernel 2: gram (R15-proven: B fragments front-loaded). Delta: row sums
// accumulated in the EPILOGUE (u's already in regs); copy-out is pure LDS+STG.
// CTA = 32 rows x 4096 cols, 256 threads, 32 tiles of 128, double-buffered.
// smem 92,928 B -> 2 CTAs/SM.
// ===========================================================================
#define OFF_B    0
#define BUF_SZ   36864
#define BLO_OFF  18432
#define OFF_AHI  73728
#define OFF_ALO  78336
#define OFF_NUM  82944
#define OFF_SQC  91648
#define OFF_SQR  92672
#define OFF_RSUM 92800
#define GRAM_SMEM 92928

__device__ __forceinline__ unsigned qexp(float arg) {
    float k;
    asm("ex2.approx.ftz.f32 %0, %1;" : "=f"(k) : "f"(arg));
    float p = fmaf(k, PA4, PA3);
    p = fmaf(k, p, PA2);
    p = fmaf(k, p, PA1);
    p = fmaf(k, p, PA0);
    return __float2uint_rn(p);
}

__global__ __launch_bounds__(256, 2) void gram_kernel()
{
    extern __shared__ char sm[];
    const uint32_t smu = smem_u32(sm);

    float* sqp_r = (float*)(sm + OFF_SQR);
    int*   rsum  = (int*)  (sm + OFF_RSUM);

    const int t    = threadIdx.x;
    const int lane = t & 31, warp = t >> 5;
    const int b    = blockIdx.x >> 7;
    const int r0   = (blockIdx.x & 127) * 32;
    const int gr   = lane >> 2;

    // ---- stage A + sqp_r + init rowsum ----
    {
        const int row = t >> 3, seg = t & 7;
        const size_t src = ((size_t)(b * NPTS + r0 + row) << 6) + seg * 8;
        const int dsto = (row * ASTR + seg * 8) * 2;
        *(uint4*)(sm + OFF_AHI + dsto) = *(const uint4*)(g_zhi + src);
        *(uint4*)(sm + OFF_ALO + dsto) = *(const uint4*)(g_zlo + src);
    }
    if (t < 32) { sqp_r[t] = g_sq[b * NPTS + r0 + t]; rsum[t] = 0; }

    // ---- prologue: prefetch tiles 0 and 1 ----
    #pragma unroll
    for (int pt = 0; pt < 2; pt++) {
        const uint32_t bbase = smu + OFF_B + pt * BUF_SZ;
        #pragma unroll
        for (int i = 0; i < 4; i++) {
            const int idx = i * 256 + t;
            const int rr = idx >> 3, seg = idx & 7;
            const size_t src = ((size_t)(b * NPTS + pt * 128 + rr) << 6) + seg * 8;
            const uint32_t dsto = (rr * BSTR + seg * 8) * 2;
            cp16(bbase + dsto, g_zhi + src);
            cp16(bbase + BLO_OFF + dsto, g_zlo + src);
        }
        if (t < 128) cp4(smu + OFF_SQC + pt * 512 + t * 4, g_sq + b * NPTS + pt * 128 + t);
        cp_commit();
    }
    __syncthreads();

    // ---- hoist A fragments (tile-invariant) ----
    const int a_lr = (lane & 7) + ((lane >> 3) & 1) * 8;
    const int a_lc = (lane >> 4) * 8;
    uint32_t afh[2][4][4], afl[2][4][4];
    #pragma unroll
    for (int ms = 0; ms < 2; ms++)
        #pragma unroll
        for (int ks = 0; ks < 4; ks++) {
            const uint32_t ao = ((ms * 16 + a_lr) * ASTR + ks * 16 + a_lc) * 2;
            ldsm_x4(smu + OFF_AHI + ao, afh[ms][ks]);
            ldsm_x4(smu + OFF_ALO + ao, afl[ms][ks]);
        }

    const int b_lr = warp * 16 + (lane & 7) + ((lane >> 4) & 1) * 8;
    const int b_lc = ((lane >> 3) & 1) * 8;

    // epilogue-side row-sum partials: [ms][half] -> row = ms*16 + half*8 + gr
    int sp[2][2] = {{0, 0}, {0, 0}};

    for (int tile = 0; tile < 32; tile++) {
        const int col0 = tile * 128;
        const int buf  = tile & 1;
        const uint32_t bbase = smu + OFF_B + buf * BUF_SZ;
        const float* sqp_c = (const float*)(sm + OFF_SQC + buf * 512);

        cp_wait1();
        __syncthreads();

        // ---- load ALL B fragments for this tile up front (8 ldsm) ----
        uint32_t bfh[4][4], bfl[4][4];
        #pragma unroll
        for (int ks = 0; ks < 4; ks++) {
            const uint32_t bo = (b_lr * BSTR + ks * 16 + b_lc) * 2;
            ldsm_x4(bbase + bo, bfh[ks]);
            ldsm_x4(bbase + BLO_OFF + bo, bfl[ks]);
        }

        // ---- uninterrupted 48-mma chain ----
        float acc[2][2][4];
        #pragma unroll
        for (int ms = 0; ms < 2; ms++)
            #pragma unroll
            for (int ns = 0; ns < 2; ns++)
                #pragma unroll
                for (int q = 0; q < 4; q++) acc[ms][ns][q] = 0.f;

        #pragma unroll
        for (int ks = 0; ks < 4; ks++) {
            #pragma unroll
            for (int ms = 0; ms < 2; ms++) {
                mma_bf16(acc[ms][0], afh[ms][ks], &bfh[ks][0]);
                mma_bf16(acc[ms][1], afh[ms][ks], &bfh[ks][2]);
                mma_bf16(acc[ms][0], afh[ms][ks], &bfl[ks][0]);
                mma_bf16(acc[ms][1], afh[ms][ks], &bfl[ks][2]);
                mma_bf16(acc[ms][0], afl[ms][ks], &bfh[ks][0]);
                mma_bf16(acc[ms][1], afl[ms][ks], &bfh[ks][2]);
            }
        }

        // ---- epilogue: qexp + u16 pack + row-sum accumulate ----
        #pragma unroll
        for (int ms = 0; ms < 2; ms++) {
            const int ra = ms * 16 + gr;
            const float rr0 = sqp_r[ra], rr1 = sqp_r[ra + 8];
            #pragma unroll
            for (int ns = 0; ns < 2; ns++) {
                const int col = warp * 16 + ns * 8 + (lane & 3) * 2;
                const float rs00 = rr0 + sqp_c[col], rs01 = rr0 + sqp_c[col + 1];
                const float rs10 = rr1 + sqp_c[col], rs11 = rr1 + sqp_c[col + 1];
                unsigned u0 = qexp(acc[ms][ns][0] + rs00);
                unsigned u1 = qexp(acc[ms][ns][1] + rs01);
                unsigned u2 = qexp(acc[ms][ns][2] + rs10);
                unsigned u3 = qexp(acc[ms][ns][3] + rs11);
                sp[ms][0] += (int)(u0 + u1);
                sp[ms][1] += (int)(u2 + u3);
                *(uint32_t*)(sm + OFF_NUM + (ra * NSTR + col) * 2)       = u0 | (u1 << 16);
                *(uint32_t*)(sm + OFF_NUM + ((ra + 8) * NSTR + col) * 2) = u2 | (u3 << 16);
            }
        }
        __syncthreads();

        // ---- prefetch tile+2 ----
        if (tile < 30) {
            #pragma unroll
            for (int i = 0; i < 4; i++) {
                const int idx = i * 256 + t;
                const int rr = idx >> 3, seg = idx & 7;
                const size_t src = ((size_t)(b * NPTS + col0 + 256 + rr) << 6) + seg * 8;
                const uint32_t dsto = (rr * BSTR + seg * 8) * 2;
                cp16(bbase + dsto, g_zhi + src);
                cp16(bbase + BLO_OFF + dsto, g_zlo + src);
            }
            if (t < 128) cp4(smu + OFF_SQC + buf * 512 + t * 4,
                             g_sq + b * NPTS + col0 + 256 + t);
        }
        cp_commit();

        // ---- copy-out: pure LDS.128 + STG.128 (no adds) ----
        {
            const int row = t >> 3, cbase = (t & 7) * 16;
            unsigned short* gdst = g_num +
                ((size_t)(b * NPTS + r0 + row) << 12) + col0 + cbase;
            #pragma unroll
            for (int j = 0; j < 2; j++) {
                uint4 v = *(const uint4*)(sm + OFF_NUM + (row * NSTR + cbase + j * 8) * 2);
                *(uint4*)(gdst + j * 8) = v;
            }
        }
    }

    // ---- final row-sum reduce: quad-shfl then atomic (4 per lane-group) ----
    #pragma unroll
    for (int ms = 0; ms < 2; ms++)
        #pragma unroll
        for (int h = 0; h < 2; h++) {
            int s = sp[ms][h];
            s += __shfl_xor_sync(0xFFFFFFFFu, s, 1);
            s += __shfl_xor_sync(0xFFFFFFFFu, s, 2);
            if ((lane & 3) == 0) atomicAdd(&rsum[ms * 16 + h * 8 + gr], s);
        }
    __syncthreads();

    if (t < 32)
        g_scale[b * NPTS + r0 + t] = INV_RENORM / (float)rsum[t];
}

// ===========================================================================
// Kernel 3: rescale u16 numerators -> float output.
// 512 threads, 2 independent uint4 per thread, grid 8192.
// ===========================================================================
__global__ __launch_bounds__(512) void rescale_kernel(float* __restrict__ out)
{
    const float bias = 1e-6f * INV_RENORM;
    const size_t base = (size_t)blockIdx.x * 1024 + threadIdx.x;
    #pragma unroll
    for (int h = 0; h < 2; h++) {
        const size_t idx = base + h * 512;
        const size_t row = idx >> 9;
        const uint4 v = ((const uint4*)g_num)[idx];
        const float s = g_scale[row];
        float4 o0, o1;
        o0.x = fmaf((float)(v.x & 0xFFFFu), s, bias);
        o0.y = fmaf((float)(v.x >> 16),     s, bias);
        o0.z = fmaf((float)(v.y & 0xFFFFu), s, bias);
        o0.w = fmaf((float)(v.y >> 16),     s, bias);
        o1.x = fmaf((float)(v.z & 0xFFFFu), s, bias);
        o1.y = fmaf((float)(v.z >> 16),     s, bias);
        o1.z = fmaf((float)(v.w & 0xFFFFu), s, bias);
        o1.w = fmaf((float)(v.w >> 16),     s, bias);
        ((float4*)out)[idx * 2]     = o0;
        ((float4*)out)[idx * 2 + 1] = o1;
    }
}

// ===========================================================================
extern "C" void kernel_launch(void* const* d_in, const int* in_sizes, int n_in,
                              void* d_out, int out_size)
{
    const float* emb = (const float*)d_in[0];
    const float* W1  = (const float*)d_in[1];
    const float* b1  = (const float*)d_in[2];
    const float* W2  = (const float*)d_in[3];
    const float* b2  = (const float*)d_in[4];
    const float* W3  = (const float*)d_in[5];
    const float* b3  = (const float*)d_in[6];
    float* out = (float*)d_out;

    cudaFuncSetAttribute(mlp_kernel,  cudaFuncAttributeMaxDynamicSharedMemorySize, MLP_SMEM);
    cudaFuncSetAttribute(gram_kernel, cudaFuncAttributeMaxDynamicSharedMemorySize, GRAM_SMEM);

    mlp_kernel<<<512, 512, MLP_SMEM>>>(emb, W1, b1, W2, b2, W3, b3);
    gram_kernel<<<512, 256, GRAM_SMEM>>>();
    rescale_kernel<<<8192, 512>>>(out);
}